// round 1
// baseline (speedup 1.0000x reference)
#include <cuda_runtime.h>
#include <math.h>
#include <stdint.h>

// Problem constants
#define B_   4
#define S_   2048
#define H_   2048
#define NH_  16
#define NKV_ 4
#define HD_  128
#define F_   3072          // H + 2*NKV*HD
#define GRP_ 4             // NH / NKV

// Scratch (device globals: allocation-free per harness rules)
__device__ float g_qkv[(size_t)B_ * S_ * F_];          // [B*S, 3072]
__device__ float g_q[(size_t)B_ * NH_ * S_ * HD_];     // [B,NH,S,HD]
__device__ float g_k[(size_t)B_ * NKV_ * S_ * HD_];    // [B,NKV,S,HD]
__device__ float g_v[(size_t)B_ * NKV_ * S_ * HD_];    // [B,NKV,S,HD]
__device__ float g_o[(size_t)B_ * S_ * H_];            // [B*S, NH*HD]

// ---------------------------------------------------------------------------
// SGEMM: C[M,N] = A[M,K] @ B[K,N], row-major fp32.
// 128x128 block tile, BK=8, 8x8 thread tile, 256 threads.
// Requires M%128==0, N%128==0, K%8==0 (true for all our shapes).
// ---------------------------------------------------------------------------
__global__ __launch_bounds__(256) void sgemm128(
    const float* __restrict__ A, const float* __restrict__ B,
    float* __restrict__ C, int M, int N, int K)
{
    __shared__ float As[8][128];   // transposed A tile: As[k][m]
    __shared__ float Bs[8][128];   // Bs[k][n]

    const int tid = threadIdx.x;
    const int bm = blockIdx.y * 128;
    const int bn = blockIdx.x * 128;

    const int aRow = tid >> 1;            // 0..127
    const int aCol = (tid & 1) * 4;       // 0 or 4
    const int bRow = tid >> 5;            // 0..7
    const int bCol = (tid & 31) * 4;      // 0..124

    const float* Aptr = A + (size_t)(bm + aRow) * K + aCol;
    const float* Bptr = B + (size_t)bRow * N + bn + bCol;

    const int ty = tid >> 4;      // 0..15
    const int tx = tid & 15;      // 0..15

    float acc[8][8];
    #pragma unroll
    for (int i = 0; i < 8; i++)
        #pragma unroll
        for (int j = 0; j < 8; j++) acc[i][j] = 0.f;

    for (int k0 = 0; k0 < K; k0 += 8) {
        float4 a = *(const float4*)Aptr;
        As[aCol + 0][aRow] = a.x;
        As[aCol + 1][aRow] = a.y;
        As[aCol + 2][aRow] = a.z;
        As[aCol + 3][aRow] = a.w;
        *(float4*)(&Bs[bRow][bCol]) = *(const float4*)Bptr;
        __syncthreads();

        #pragma unroll
        for (int k = 0; k < 8; k++) {
            float ra[8], rb[8];
            *(float4*)(ra)     = *(const float4*)(&As[k][ty * 8]);
            *(float4*)(ra + 4) = *(const float4*)(&As[k][ty * 8 + 4]);
            *(float4*)(rb)     = *(const float4*)(&Bs[k][tx * 8]);
            *(float4*)(rb + 4) = *(const float4*)(&Bs[k][tx * 8 + 4]);
            #pragma unroll
            for (int i = 0; i < 8; i++)
                #pragma unroll
                for (int j = 0; j < 8; j++)
                    acc[i][j] = fmaf(ra[i], rb[j], acc[i][j]);
        }
        __syncthreads();
        Aptr += 8;
        Bptr += (size_t)8 * N;
    }

    #pragma unroll
    for (int i = 0; i < 8; i++) {
        float* cp = C + (size_t)(bm + ty * 8 + i) * N + bn + tx * 8;
        float4 o0 = make_float4(acc[i][0], acc[i][1], acc[i][2], acc[i][3]);
        float4 o1 = make_float4(acc[i][4], acc[i][5], acc[i][6], acc[i][7]);
        *(float4*)(cp)     = o0;
        *(float4*)(cp + 4) = o1;
    }
}

// ---------------------------------------------------------------------------
// RoPE + split/scatter: qkv [B*S, 3072] -> q [B,NH,S,HD], k/v [B,NKV,S,HD]
// Per token layout: NKV groups of (4*HD q | HD k | HD v) = 768 floats.
// ---------------------------------------------------------------------------
__global__ __launch_bounds__(256) void rope_split(
    const float* __restrict__ qkv, const float* __restrict__ rope_cos,
    const float* __restrict__ rope_sin,
    float* __restrict__ q_out, float* __restrict__ k_out, float* __restrict__ v_out)
{
    const int tok = blockIdx.x;          // b*S + s
    const int b = tok >> 11;             // / 2048
    const int s = tok & 2047;

    __shared__ float shc[HD_], shs[HD_];
    if (threadIdx.x < 128)      shc[threadIdx.x] = rope_cos[(size_t)s * HD_ + threadIdx.x];
    else                        shs[threadIdx.x - 128] = rope_sin[(size_t)s * HD_ + threadIdx.x - 128];
    __syncthreads();

    const float* base = qkv + (size_t)tok * F_;

    // Q heads
    for (int idx = threadIdx.x; idx < NH_ * HD_; idx += 256) {
        int hh = idx >> 7, d = idx & 127;
        int j = hh >> 2, i = hh & 3;
        const float* qp = base + j * 768 + i * 128;
        float x = qp[d];
        float other = (d < 64) ? -qp[d + 64] : qp[d - 64];
        q_out[(((size_t)b * NH_ + hh) * S_ + s) * HD_ + d] = x * shc[d] + other * shs[d];
    }
    // K (RoPE) and V (copy)
    for (int idx = threadIdx.x; idx < NKV_ * HD_; idx += 256) {
        int j = idx >> 7, d = idx & 127;
        const float* kp = base + j * 768 + 512;
        float x = kp[d];
        float other = (d < 64) ? -kp[d + 64] : kp[d - 64];
        size_t off = (((size_t)b * NKV_ + j) * S_ + s) * HD_ + d;
        k_out[off] = x * shc[d] + other * shs[d];
        v_out[off] = kp[128 + d];
    }
}

// ---------------------------------------------------------------------------
// Causal flash attention, fp32, GQA (4 q-heads per kv-head).
// Block: 64 query rows x iterate over 64-key tiles (only kt <= qt).
// 256 threads: (ty,tx) 16x16; thread computes 4x4 scores, owns 4 rows x 8 dims of O.
// Q,K stored d-major (transposed) in smem for conflict-free LDS.
// Output written directly in [B, S, NH*HD] layout for the projection GEMM.
// ---------------------------------------------------------------------------
#define TS_ 68   // padded stride for transposed tiles (128 x 64 -> stride 68)

__global__ __launch_bounds__(256) void flash_kernel(
    const float* __restrict__ Q, const float* __restrict__ K,
    const float* __restrict__ V, float* __restrict__ O)
{
    extern __shared__ float sm[];
    float* sQT = sm;                    // [128][TS_]
    float* sKT = sQT + 128 * TS_;       // [128][TS_]
    float* sV  = sKT + 128 * TS_;       // [64][128]
    float* sP  = sV + 64 * 128;         // [64][64]

    const int tid = threadIdx.x;
    const int qt = blockIdx.x;          // query tile (0..31)
    const int h  = blockIdx.y;          // q head
    const int b  = blockIdx.z;
    const int kvh = h >> 2;
    const float scale = 0.08838834764831845f;  // 1/sqrt(128)

    const float* Qbase = Q + (((size_t)b * NH_ + h) * S_ + (size_t)qt * 64) * HD_;
    const float* Kbase = K + (((size_t)b * NKV_ + kvh) * S_) * HD_;
    const float* Vbase = V + (((size_t)b * NKV_ + kvh) * S_) * HD_;

    // Load Q tile transposed & pre-scaled. i = d4*64 + row; stores conflict-free.
    for (int i = tid; i < 32 * 64; i += 256) {
        int d4 = i >> 6, r = i & 63;
        float4 q4 = *(const float4*)(Qbase + (size_t)r * HD_ + d4 * 4);
        sQT[(d4 * 4 + 0) * TS_ + r] = q4.x * scale;
        sQT[(d4 * 4 + 1) * TS_ + r] = q4.y * scale;
        sQT[(d4 * 4 + 2) * TS_ + r] = q4.z * scale;
        sQT[(d4 * 4 + 3) * TS_ + r] = q4.w * scale;
    }

    const int ty = tid >> 4, tx = tid & 15;
    const int r0 = ty * 4, c0 = tx * 4;

    float m[4] = {-INFINITY, -INFINITY, -INFINITY, -INFINITY};
    float l[4] = {0.f, 0.f, 0.f, 0.f};
    float acc[4][8];
    #pragma unroll
    for (int i = 0; i < 4; i++)
        #pragma unroll
        for (int j = 0; j < 8; j++) acc[i][j] = 0.f;

    __syncthreads();

    for (int kt = 0; kt <= qt; kt++) {
        // Load K tile transposed, V tile row-major
        const float* Kt = Kbase + (size_t)kt * 64 * HD_;
        const float* Vt = Vbase + (size_t)kt * 64 * HD_;
        for (int i = tid; i < 32 * 64; i += 256) {
            int d4 = i >> 6, r = i & 63;
            float4 k4 = *(const float4*)(Kt + (size_t)r * HD_ + d4 * 4);
            sKT[(d4 * 4 + 0) * TS_ + r] = k4.x;
            sKT[(d4 * 4 + 1) * TS_ + r] = k4.y;
            sKT[(d4 * 4 + 2) * TS_ + r] = k4.z;
            sKT[(d4 * 4 + 3) * TS_ + r] = k4.w;
        }
        for (int i = tid; i < 64 * 32; i += 256) {
            int r = i >> 5, d4 = i & 31;
            *(float4*)(sV + r * HD_ + d4 * 4) = *(const float4*)(Vt + (size_t)r * HD_ + d4 * 4);
        }
        __syncthreads();

        // Scores: s[i][j] = sum_d Q[r0+i][d] * K[c0+j][d]  (Q pre-scaled)
        float sc[4][4];
        #pragma unroll
        for (int i = 0; i < 4; i++)
            #pragma unroll
            for (int j = 0; j < 4; j++) sc[i][j] = 0.f;

        #pragma unroll 4
        for (int d = 0; d < HD_; d++) {
            float qa[4], kb[4];
            *(float4*)qa = *(const float4*)(sQT + d * TS_ + r0);
            *(float4*)kb = *(const float4*)(sKT + d * TS_ + c0);
            #pragma unroll
            for (int i = 0; i < 4; i++)
                #pragma unroll
                for (int j = 0; j < 4; j++)
                    sc[i][j] = fmaf(qa[i], kb[j], sc[i][j]);
        }

        // Causal mask only matters on the diagonal tile
        if (kt == qt) {
            #pragma unroll
            for (int i = 0; i < 4; i++)
                #pragma unroll
                for (int j = 0; j < 4; j++)
                    if (c0 + j > r0 + i) sc[i][j] = -1e30f;
        }

        // Online softmax per row (reduce across the 16 tx lanes)
        #pragma unroll
        for (int i = 0; i < 4; i++) {
            float mloc = fmaxf(fmaxf(sc[i][0], sc[i][1]), fmaxf(sc[i][2], sc[i][3]));
            #pragma unroll
            for (int off = 1; off < 16; off <<= 1)
                mloc = fmaxf(mloc, __shfl_xor_sync(0xffffffffu, mloc, off));
            float mnew = fmaxf(m[i], mloc);
            float p0 = __expf(sc[i][0] - mnew);
            float p1 = __expf(sc[i][1] - mnew);
            float p2 = __expf(sc[i][2] - mnew);
            float p3 = __expf(sc[i][3] - mnew);
            float rs = (p0 + p1) + (p2 + p3);
            #pragma unroll
            for (int off = 1; off < 16; off <<= 1)
                rs += __shfl_xor_sync(0xffffffffu, rs, off);
            float alpha = __expf(m[i] - mnew);
            l[i] = l[i] * alpha + rs;
            m[i] = mnew;
            #pragma unroll
            for (int jj = 0; jj < 8; jj++) acc[i][jj] *= alpha;
            float4 pv = make_float4(p0, p1, p2, p3);
            *(float4*)(sP + (r0 + i) * 64 + c0) = pv;
        }
        __syncthreads();

        // O += P @ V
        #pragma unroll 2
        for (int k0 = 0; k0 < 64; k0 += 4) {
            float pr[4][4];
            #pragma unroll
            for (int i = 0; i < 4; i++)
                *(float4*)pr[i] = *(const float4*)(sP + (r0 + i) * 64 + k0);
            #pragma unroll
            for (int kk = 0; kk < 4; kk++) {
                float vv[8];
                *(float4*)(vv)     = *(const float4*)(sV + (k0 + kk) * HD_ + tx * 8);
                *(float4*)(vv + 4) = *(const float4*)(sV + (k0 + kk) * HD_ + tx * 8 + 4);
                #pragma unroll
                for (int i = 0; i < 4; i++)
                    #pragma unroll
                    for (int jj = 0; jj < 8; jj++)
                        acc[i][jj] = fmaf(pr[i][kk], vv[jj], acc[i][jj]);
            }
        }
        __syncthreads();
    }

    // Write O / l into [B, S, NH*HD]
    #pragma unroll
    for (int i = 0; i < 4; i++) {
        float inv = 1.f / l[i];
        int row = qt * 64 + r0 + i;
        float* outp = O + ((size_t)b * S_ + row) * H_ + h * HD_ + tx * 8;
        float4 o0 = make_float4(acc[i][0] * inv, acc[i][1] * inv, acc[i][2] * inv, acc[i][3] * inv);
        float4 o1 = make_float4(acc[i][4] * inv, acc[i][5] * inv, acc[i][6] * inv, acc[i][7] * inv);
        *(float4*)(outp)     = o0;
        *(float4*)(outp + 4) = o1;
    }
}

// ---------------------------------------------------------------------------
// Launch
// ---------------------------------------------------------------------------
extern "C" void kernel_launch(void* const* d_in, const int* in_sizes, int n_in,
                              void* d_out, int out_size)
{
    (void)in_sizes; (void)n_in; (void)out_size;
    const float* hidden = (const float*)d_in[0];
    // d_in[1] = attention_mask: structurally causal, unused (exact: exp(-1e9) == 0 in fp32)
    const float* rope_cos = (const float*)d_in[2];
    const float* rope_sin = (const float*)d_in[3];
    const float* w_attn   = (const float*)d_in[4];
    const float* w_proj   = (const float*)d_in[5];
    float* out = (float*)d_out;

    float *p_qkv, *p_q, *p_k, *p_v, *p_o;
    cudaGetSymbolAddress((void**)&p_qkv, g_qkv);
    cudaGetSymbolAddress((void**)&p_q, g_q);
    cudaGetSymbolAddress((void**)&p_k, g_k);
    cudaGetSymbolAddress((void**)&p_v, g_v);
    cudaGetSymbolAddress((void**)&p_o, g_o);

    const int flash_smem = (2 * 128 * TS_ + 64 * 128 + 64 * 64) * (int)sizeof(float);
    cudaFuncSetAttribute(flash_kernel, cudaFuncAttributeMaxDynamicSharedMemorySize, flash_smem);

    // 1) QKV projection: [8192, 2048] @ [2048, 3072]
    {
        dim3 grid(F_ / 128, (B_ * S_) / 128);
        sgemm128<<<grid, 256>>>(hidden, w_attn, p_qkv, B_ * S_, F_, H_);
    }
    // 2) RoPE + head split/scatter
    rope_split<<<B_ * S_, 256>>>(p_qkv, rope_cos, rope_sin, p_q, p_k, p_v);
    // 3) Causal flash attention
    {
        dim3 grid(S_ / 64, NH_, B_);
        flash_kernel<<<grid, 256, flash_smem>>>(p_q, p_k, p_v, p_o);
    }
    // 4) Output projection: [8192, 2048] @ [2048, 2048]
    {
        dim3 grid(H_ / 128, (B_ * S_) / 128);
        sgemm128<<<grid, 256>>>(p_o, w_proj, out, B_ * S_, H_, H_);
    }
}

// round 3
// speedup vs baseline: 1.6571x; 1.6571x over previous
#include <cuda_runtime.h>
#include <cuda_bf16.h>
#include <math.h>
#include <stdint.h>

// Problem constants
#define B_   4
#define S_   2048
#define H_   2048
#define NH_  16
#define NKV_ 4
#define HD_  128
#define F_   3072          // H + 2*NKV*HD
#define KC_  64            // GEMM K-chunk (bf16: 64 elems = 128B = one SW128 atom row)

// ---------------------------------------------------------------------------
// Scratch (device globals: allocation-free per harness rules)
// ---------------------------------------------------------------------------
__device__ float g_qkv[(size_t)B_ * S_ * F_];          // [B*S, 3072]
__device__ float g_q[(size_t)B_ * NH_ * S_ * HD_];     // [B,NH,S,HD]
__device__ float g_k[(size_t)B_ * NKV_ * S_ * HD_];    // [B,NKV,S,HD]
__device__ float g_v[(size_t)B_ * NKV_ * S_ * HD_];    // [B,NKV,S,HD]
__device__ float g_o[(size_t)B_ * S_ * H_];            // [B*S, NH*HD]

__device__ __nv_bfloat16 g_x1[(size_t)B_ * S_ * H_];   // activation hi
__device__ __nv_bfloat16 g_x2[(size_t)B_ * S_ * H_];   // activation lo
__device__ __nv_bfloat16 g_wa1[(size_t)F_ * H_];       // w_attn^T hi [3072,2048]
__device__ __nv_bfloat16 g_wa2[(size_t)F_ * H_];
__device__ __nv_bfloat16 g_wp1[(size_t)H_ * H_];       // w_proj^T hi [2048,2048]
__device__ __nv_bfloat16 g_wp2[(size_t)H_ * H_];

// ---------------------------------------------------------------------------
// Arch-neutral PTX helpers (no tcgen05 — unavailable under compute_103 target)
// ---------------------------------------------------------------------------
__device__ __forceinline__ uint32_t smem_u32(const void* p) {
    uint32_t a;
    asm("{ .reg .u64 t; cvta.to.shared.u64 t, %1; cvt.u32.u64 %0, t; }" : "=r"(a) : "l"(p));
    return a;
}
__device__ __forceinline__ void cp16(uint32_t saddr, const void* g) {
    asm volatile("cp.async.cg.shared.global [%0], [%1], 16;" :: "r"(saddr), "l"(g));
}
#define CP_COMMIT() asm volatile("cp.async.commit_group;" ::: "memory")
#define CP_WAIT(n)  asm volatile("cp.async.wait_group %0;" :: "n"(n) : "memory")

__device__ __forceinline__ void ldsm_x4(uint32_t* r, uint32_t addr) {
    asm volatile("ldmatrix.sync.aligned.m8n8.x4.shared.b16 {%0,%1,%2,%3}, [%4];"
                 : "=r"(r[0]), "=r"(r[1]), "=r"(r[2]), "=r"(r[3]) : "r"(addr));
}
__device__ __forceinline__ void mma_bf16(float* c, const uint32_t* a, const uint32_t* b) {
    asm volatile(
        "mma.sync.aligned.m16n8k16.row.col.f32.bf16.bf16.f32 "
        "{%0,%1,%2,%3}, {%4,%5,%6,%7}, {%8,%9}, {%0,%1,%2,%3};"
        : "+f"(c[0]), "+f"(c[1]), "+f"(c[2]), "+f"(c[3])
        : "r"(a[0]), "r"(a[1]), "r"(a[2]), "r"(a[3]), "r"(b[0]), "r"(b[1]));
}
__device__ __forceinline__ uint32_t swz(uint32_t off) {  // SW128
    return off ^ ((off >> 3) & 0x70);
}

// ---------------------------------------------------------------------------
// bf16 split kernels
// ---------------------------------------------------------------------------
__global__ __launch_bounds__(256) void split2(
    const float* __restrict__ x, __nv_bfloat16* __restrict__ hi,
    __nv_bfloat16* __restrict__ lo, int n4)
{
    int i = blockIdx.x * 256 + threadIdx.x;
    if (i >= n4) return;
    float4 v = *((const float4*)x + i);
    __nv_bfloat16 h0 = __float2bfloat16(v.x), h1 = __float2bfloat16(v.y);
    __nv_bfloat16 h2 = __float2bfloat16(v.z), h3 = __float2bfloat16(v.w);
    __nv_bfloat16 l0 = __float2bfloat16(v.x - __bfloat162float(h0));
    __nv_bfloat16 l1 = __float2bfloat16(v.y - __bfloat162float(h1));
    __nv_bfloat16 l2 = __float2bfloat16(v.z - __bfloat162float(h2));
    __nv_bfloat16 l3 = __float2bfloat16(v.w - __bfloat162float(h3));
    __nv_bfloat162 hp0, hp1, lp0, lp1;
    hp0.x = h0; hp0.y = h1; hp1.x = h2; hp1.y = h3;
    lp0.x = l0; lp0.y = l1; lp1.x = l2; lp1.y = l3;
    ((__nv_bfloat162*)hi)[i * 2]     = hp0;
    ((__nv_bfloat162*)hi)[i * 2 + 1] = hp1;
    ((__nv_bfloat162*)lo)[i * 2]     = lp0;
    ((__nv_bfloat162*)lo)[i * 2 + 1] = lp1;
}

// transpose + split: in [K,N] fp32 row-major -> out [N,K] bf16 (hi, lo)
__global__ __launch_bounds__(256) void tsplit(
    const float* __restrict__ in, __nv_bfloat16* __restrict__ oh,
    __nv_bfloat16* __restrict__ ol, int K, int N)
{
    __shared__ float t[32][33];
    int n0 = blockIdx.x * 32, k0 = blockIdx.y * 32;
    int tx = threadIdx.x & 31, ty = threadIdx.x >> 5;
    #pragma unroll
    for (int r = ty; r < 32; r += 8)
        t[r][tx] = in[(size_t)(k0 + r) * N + n0 + tx];
    __syncthreads();
    #pragma unroll
    for (int r = ty; r < 32; r += 8) {
        float v = t[tx][r];
        __nv_bfloat16 h = __float2bfloat16(v);
        __nv_bfloat16 l = __float2bfloat16(v - __bfloat162float(h));
        size_t off = (size_t)(n0 + r) * K + k0 + tx;
        oh[off] = h;
        ol[off] = l;
    }
}

// ---------------------------------------------------------------------------
// bf16x3 GEMM on mma.sync: C[M,N] = (A1+A2)[M,K] @ (B1+B2)[N,K]^T (drop A2*B2)
// 128x128 CTA tile, KC=64, 2-stage cp.async pipeline, 8 warps (2x4),
// warp tile 64x32 via m16n8k16.
// SMEM stage: A1,A2,B1,B2 tiles of [128][64] bf16 (16KB each, SW128) = 64KB.
// ---------------------------------------------------------------------------
__global__ __launch_bounds__(256, 1) void gemm_bf16x3(
    const __nv_bfloat16* __restrict__ A1, const __nv_bfloat16* __restrict__ A2,
    const __nv_bfloat16* __restrict__ B1, const __nv_bfloat16* __restrict__ B2,
    float* __restrict__ C, int M, int N, int K)
{
    extern __shared__ __align__(128) char smem[];
    const uint32_t sbase = smem_u32(smem);
    const int tid = threadIdx.x;
    const int wid = tid >> 5, lane = tid & 31;
    const int bm = blockIdx.y * 128, bn = blockIdx.x * 128;

    const __nv_bfloat16* srcs[4] = {
        A1 + (size_t)bm * K, A2 + (size_t)bm * K,
        B1 + (size_t)bn * K, B2 + (size_t)bn * K };

    const int nchunks = K / KC_;

    auto load_stage = [&](int c, int buf) {
        const int k0 = c * KC_;
        #pragma unroll
        for (int t = 0; t < 4; t++) {
            const __nv_bfloat16* g = srcs[t] + k0;
            uint32_t db = sbase + buf * 65536 + t * 16384;
            #pragma unroll
            for (int it = 0; it < 4; it++) {
                int i = tid + it * 256;             // 0..1023 (16B chunks)
                int row = i >> 3, c8 = i & 7;
                cp16(db + swz((uint32_t)(row * 128 + c8 * 16)),
                     g + (size_t)row * K + c8 * 8);
            }
        }
    };

    load_stage(0, 0); CP_COMMIT();
    if (nchunks > 1) load_stage(1, 1);
    CP_COMMIT();

    const int wm = wid >> 2, wn = wid & 3;
    const int m0 = wm * 64, n0 = wn * 32;

    float acc[4][4][4];
    #pragma unroll
    for (int i = 0; i < 4; i++)
        #pragma unroll
        for (int j = 0; j < 4; j++)
            #pragma unroll
            for (int k = 0; k < 4; k++) acc[i][j][k] = 0.f;

    // ldmatrix lane address components
    const int aRow = (lane & 15);            // A: rows m..m+15
    const int aKb  = (lane >> 4) * 16;       // A: k-halves
    const int bRow = (lane & 7) + ((lane >> 4) & 1) * 8;  // B: rows n..n+15
    const int bKb  = ((lane >> 3) & 1) * 16;              // B: k-halves

    for (int c = 0; c < nchunks; c++) {
        CP_WAIT(1);
        __syncthreads();
        const int buf = c & 1;
        const uint32_t sA1 = sbase + buf * 65536;
        const uint32_t sA2 = sA1 + 16384;
        const uint32_t sB1 = sA1 + 32768;
        const uint32_t sB2 = sA1 + 49152;

        #pragma unroll
        for (int ks = 0; ks < 4; ks++) {
            const uint32_t akb = (uint32_t)(ks * 32 + aKb);
            const uint32_t bkb = (uint32_t)(ks * 32 + bKb);
            uint32_t a1f[4][4], a2f[4][4], b1f[2][4], b2f[2][4];
            #pragma unroll
            for (int mt = 0; mt < 4; mt++) {
                uint32_t off = swz((uint32_t)((m0 + mt * 16 + aRow) * 128) + akb);
                ldsm_x4(a1f[mt], sA1 + off);
                ldsm_x4(a2f[mt], sA2 + off);
            }
            #pragma unroll
            for (int p = 0; p < 2; p++) {
                uint32_t off = swz((uint32_t)((n0 + p * 16 + bRow) * 128) + bkb);
                ldsm_x4(b1f[p], sB1 + off);
                ldsm_x4(b2f[p], sB2 + off);
            }
            #pragma unroll
            for (int mt = 0; mt < 4; mt++)
                #pragma unroll
                for (int nt = 0; nt < 4; nt++) {
                    mma_bf16(acc[mt][nt], a1f[mt], &b1f[nt >> 1][(nt & 1) * 2]);
                    mma_bf16(acc[mt][nt], a1f[mt], &b2f[nt >> 1][(nt & 1) * 2]);
                    mma_bf16(acc[mt][nt], a2f[mt], &b1f[nt >> 1][(nt & 1) * 2]);
                }
        }
        __syncthreads();
        if (c + 2 < nchunks) load_stage(c + 2, buf);
        CP_COMMIT();
    }

    // Epilogue: fp32 stores (c0,c1 -> row, cols j,j+1; c2,c3 -> row+8)
    const int er = lane >> 2, ec = (lane & 3) * 2;
    #pragma unroll
    for (int mt = 0; mt < 4; mt++)
        #pragma unroll
        for (int nt = 0; nt < 4; nt++) {
            int row = bm + m0 + mt * 16 + er;
            int col = bn + n0 + nt * 8 + ec;
            *(float2*)(C + (size_t)row * N + col) =
                make_float2(acc[mt][nt][0], acc[mt][nt][1]);
            *(float2*)(C + (size_t)(row + 8) * N + col) =
                make_float2(acc[mt][nt][2], acc[mt][nt][3]);
        }
}

// ---------------------------------------------------------------------------
// RoPE + split/scatter: qkv [B*S, 3072] -> q [B,NH,S,HD], k/v [B,NKV,S,HD]
// ---------------------------------------------------------------------------
__global__ __launch_bounds__(256) void rope_split(
    const float* __restrict__ qkv, const float* __restrict__ rope_cos,
    const float* __restrict__ rope_sin,
    float* __restrict__ q_out, float* __restrict__ k_out, float* __restrict__ v_out)
{
    const int tok = blockIdx.x;
    const int b = tok >> 11;
    const int s = tok & 2047;

    __shared__ float shc[HD_], shs[HD_];
    if (threadIdx.x < 128)      shc[threadIdx.x] = rope_cos[(size_t)s * HD_ + threadIdx.x];
    else                        shs[threadIdx.x - 128] = rope_sin[(size_t)s * HD_ + threadIdx.x - 128];
    __syncthreads();

    const float* base = qkv + (size_t)tok * F_;

    for (int idx = threadIdx.x; idx < NH_ * HD_; idx += 256) {
        int hh = idx >> 7, d = idx & 127;
        int j = hh >> 2, i = hh & 3;
        const float* qp = base + j * 768 + i * 128;
        float x = qp[d];
        float other = (d < 64) ? -qp[d + 64] : qp[d - 64];
        q_out[(((size_t)b * NH_ + hh) * S_ + s) * HD_ + d] = x * shc[d] + other * shs[d];
    }
    for (int idx = threadIdx.x; idx < NKV_ * HD_; idx += 256) {
        int j = idx >> 7, d = idx & 127;
        const float* kp = base + j * 768 + 512;
        float x = kp[d];
        float other = (d < 64) ? -kp[d + 64] : kp[d - 64];
        size_t off = (((size_t)b * NKV_ + j) * S_ + s) * HD_ + d;
        k_out[off] = x * shc[d] + other * shs[d];
        v_out[off] = kp[128 + d];
    }
}

// ---------------------------------------------------------------------------
// Causal flash attention, fp32, GQA — unchanged (passing, rel_err 1.6e-6)
// ---------------------------------------------------------------------------
#define TS_ 68

__global__ __launch_bounds__(256) void flash_kernel(
    const float* __restrict__ Q, const float* __restrict__ K,
    const float* __restrict__ V, float* __restrict__ O)
{
    extern __shared__ float sm[];
    float* sQT = sm;
    float* sKT = sQT + 128 * TS_;
    float* sV  = sKT + 128 * TS_;
    float* sP  = sV + 64 * 128;

    const int tid = threadIdx.x;
    const int qt = blockIdx.x;
    const int h  = blockIdx.y;
    const int b  = blockIdx.z;
    const int kvh = h >> 2;
    const float scale = 0.08838834764831845f;

    const float* Qbase = Q + (((size_t)b * NH_ + h) * S_ + (size_t)qt * 64) * HD_;
    const float* Kbase = K + (((size_t)b * NKV_ + kvh) * S_) * HD_;
    const float* Vbase = V + (((size_t)b * NKV_ + kvh) * S_) * HD_;

    for (int i = tid; i < 32 * 64; i += 256) {
        int d4 = i >> 6, r = i & 63;
        float4 q4 = *(const float4*)(Qbase + (size_t)r * HD_ + d4 * 4);
        sQT[(d4 * 4 + 0) * TS_ + r] = q4.x * scale;
        sQT[(d4 * 4 + 1) * TS_ + r] = q4.y * scale;
        sQT[(d4 * 4 + 2) * TS_ + r] = q4.z * scale;
        sQT[(d4 * 4 + 3) * TS_ + r] = q4.w * scale;
    }

    const int ty = tid >> 4, tx = tid & 15;
    const int r0 = ty * 4, c0 = tx * 4;

    float m[4] = {-INFINITY, -INFINITY, -INFINITY, -INFINITY};
    float l[4] = {0.f, 0.f, 0.f, 0.f};
    float acc[4][8];
    #pragma unroll
    for (int i = 0; i < 4; i++)
        #pragma unroll
        for (int j = 0; j < 8; j++) acc[i][j] = 0.f;

    __syncthreads();

    for (int kt = 0; kt <= qt; kt++) {
        const float* Kt = Kbase + (size_t)kt * 64 * HD_;
        const float* Vt = Vbase + (size_t)kt * 64 * HD_;
        for (int i = tid; i < 32 * 64; i += 256) {
            int d4 = i >> 6, r = i & 63;
            float4 k4 = *(const float4*)(Kt + (size_t)r * HD_ + d4 * 4);
            sKT[(d4 * 4 + 0) * TS_ + r] = k4.x;
            sKT[(d4 * 4 + 1) * TS_ + r] = k4.y;
            sKT[(d4 * 4 + 2) * TS_ + r] = k4.z;
            sKT[(d4 * 4 + 3) * TS_ + r] = k4.w;
        }
        for (int i = tid; i < 64 * 32; i += 256) {
            int r = i >> 5, d4 = i & 31;
            *(float4*)(sV + r * HD_ + d4 * 4) = *(const float4*)(Vt + (size_t)r * HD_ + d4 * 4);
        }
        __syncthreads();

        float sc[4][4];
        #pragma unroll
        for (int i = 0; i < 4; i++)
            #pragma unroll
            for (int j = 0; j < 4; j++) sc[i][j] = 0.f;

        #pragma unroll 4
        for (int d = 0; d < HD_; d++) {
            float qa[4], kb[4];
            *(float4*)qa = *(const float4*)(sQT + d * TS_ + r0);
            *(float4*)kb = *(const float4*)(sKT + d * TS_ + c0);
            #pragma unroll
            for (int i = 0; i < 4; i++)
                #pragma unroll
                for (int j = 0; j < 4; j++)
                    sc[i][j] = fmaf(qa[i], kb[j], sc[i][j]);
        }

        if (kt == qt) {
            #pragma unroll
            for (int i = 0; i < 4; i++)
                #pragma unroll
                for (int j = 0; j < 4; j++)
                    if (c0 + j > r0 + i) sc[i][j] = -1e30f;
        }

        #pragma unroll
        for (int i = 0; i < 4; i++) {
            float mloc = fmaxf(fmaxf(sc[i][0], sc[i][1]), fmaxf(sc[i][2], sc[i][3]));
            #pragma unroll
            for (int off = 1; off < 16; off <<= 1)
                mloc = fmaxf(mloc, __shfl_xor_sync(0xffffffffu, mloc, off));
            float mnew = fmaxf(m[i], mloc);
            float p0 = __expf(sc[i][0] - mnew);
            float p1 = __expf(sc[i][1] - mnew);
            float p2 = __expf(sc[i][2] - mnew);
            float p3 = __expf(sc[i][3] - mnew);
            float rs = (p0 + p1) + (p2 + p3);
            #pragma unroll
            for (int off = 1; off < 16; off <<= 1)
                rs += __shfl_xor_sync(0xffffffffu, rs, off);
            float alpha = __expf(m[i] - mnew);
            l[i] = l[i] * alpha + rs;
            m[i] = mnew;
            #pragma unroll
            for (int jj = 0; jj < 8; jj++) acc[i][jj] *= alpha;
            float4 pv = make_float4(p0, p1, p2, p3);
            *(float4*)(sP + (r0 + i) * 64 + c0) = pv;
        }
        __syncthreads();

        #pragma unroll 2
        for (int k0 = 0; k0 < 64; k0 += 4) {
            float pr[4][4];
            #pragma unroll
            for (int i = 0; i < 4; i++)
                *(float4*)pr[i] = *(const float4*)(sP + (r0 + i) * 64 + k0);
            #pragma unroll
            for (int kk = 0; kk < 4; kk++) {
                float vv[8];
                *(float4*)(vv)     = *(const float4*)(sV + (k0 + kk) * HD_ + tx * 8);
                *(float4*)(vv + 4) = *(const float4*)(sV + (k0 + kk) * HD_ + tx * 8 + 4);
                #pragma unroll
                for (int i = 0; i < 4; i++)
                    #pragma unroll
                    for (int jj = 0; jj < 8; jj++)
                        acc[i][jj] = fmaf(pr[i][kk], vv[jj], acc[i][jj]);
            }
        }
        __syncthreads();
    }

    #pragma unroll
    for (int i = 0; i < 4; i++) {
        float inv = 1.f / l[i];
        int row = qt * 64 + r0 + i;
        float* outp = O + ((size_t)b * S_ + row) * H_ + h * HD_ + tx * 8;
        float4 o0 = make_float4(acc[i][0] * inv, acc[i][1] * inv, acc[i][2] * inv, acc[i][3] * inv);
        float4 o1 = make_float4(acc[i][4] * inv, acc[i][5] * inv, acc[i][6] * inv, acc[i][7] * inv);
        *(float4*)(outp)     = o0;
        *(float4*)(outp + 4) = o1;
    }
}

// ---------------------------------------------------------------------------
// Launch
// ---------------------------------------------------------------------------
extern "C" void kernel_launch(void* const* d_in, const int* in_sizes, int n_in,
                              void* d_out, int out_size)
{
    (void)in_sizes; (void)n_in; (void)out_size;
    const float* hidden   = (const float*)d_in[0];
    // d_in[1] = attention_mask: structurally causal, unused (exp(-1e9) == 0 in fp32)
    const float* rope_cos = (const float*)d_in[2];
    const float* rope_sin = (const float*)d_in[3];
    const float* w_attn   = (const float*)d_in[4];
    const float* w_proj   = (const float*)d_in[5];
    float* out = (float*)d_out;

    float *p_qkv, *p_q, *p_k, *p_v, *p_o;
    __nv_bfloat16 *p_x1, *p_x2, *p_wa1, *p_wa2, *p_wp1, *p_wp2;
    cudaGetSymbolAddress((void**)&p_qkv, g_qkv);
    cudaGetSymbolAddress((void**)&p_q, g_q);
    cudaGetSymbolAddress((void**)&p_k, g_k);
    cudaGetSymbolAddress((void**)&p_v, g_v);
    cudaGetSymbolAddress((void**)&p_o, g_o);
    cudaGetSymbolAddress((void**)&p_x1, g_x1);
    cudaGetSymbolAddress((void**)&p_x2, g_x2);
    cudaGetSymbolAddress((void**)&p_wa1, g_wa1);
    cudaGetSymbolAddress((void**)&p_wa2, g_wa2);
    cudaGetSymbolAddress((void**)&p_wp1, g_wp1);
    cudaGetSymbolAddress((void**)&p_wp2, g_wp2);

    const int gemm_smem = 2 * 65536;                              // 128 KB
    cudaFuncSetAttribute(gemm_bf16x3, cudaFuncAttributeMaxDynamicSharedMemorySize, gemm_smem);
    const int flash_smem = (2 * 128 * TS_ + 64 * 128 + 64 * 64) * (int)sizeof(float);
    cudaFuncSetAttribute(flash_kernel, cudaFuncAttributeMaxDynamicSharedMemorySize, flash_smem);

    const int MTOK = B_ * S_;                                     // 8192

    // 0) weight prep: transpose+split
    tsplit<<<dim3(F_ / 32, H_ / 32), 256>>>(w_attn, p_wa1, p_wa2, H_, F_);
    tsplit<<<dim3(H_ / 32, H_ / 32), 256>>>(w_proj, p_wp1, p_wp2, H_, H_);
    split2<<<(MTOK * H_ / 4 + 255) / 256, 256>>>(hidden, p_x1, p_x2, MTOK * H_ / 4);

    // 1) QKV projection (tensor cores): [8192,2048] @ [2048,3072]
    gemm_bf16x3<<<dim3(F_ / 128, MTOK / 128), 256, gemm_smem>>>(
        p_x1, p_x2, p_wa1, p_wa2, p_qkv, MTOK, F_, H_);

    // 2) RoPE + head split/scatter
    rope_split<<<B_ * S_, 256>>>(p_qkv, rope_cos, rope_sin, p_q, p_k, p_v);

    // 3) Causal flash attention
    flash_kernel<<<dim3(S_ / 64, NH_, B_), 256, flash_smem>>>(p_q, p_k, p_v, p_o);

    // 4) attention output split + projection: [8192,2048] @ [2048,2048]
    split2<<<(MTOK * H_ / 4 + 255) / 256, 256>>>(p_o, p_x1, p_x2, MTOK * H_ / 4);
    gemm_bf16x3<<<dim3(H_ / 128, MTOK / 128), 256, gemm_smem>>>(
        p_x1, p_x2, p_wp1, p_wp2, out, MTOK, H_, H_);
}

// round 4
// speedup vs baseline: 3.8371x; 2.3155x over previous
#include <cuda_runtime.h>
#include <cuda_bf16.h>
#include <math.h>
#include <stdint.h>

// Problem constants
#define B_   4
#define S_   2048
#define H_   2048
#define NH_  16
#define NKV_ 4
#define HD_  128
#define F_   3072          // H + 2*NKV*HD
#define KC_  64            // GEMM K-chunk

// ---------------------------------------------------------------------------
// Scratch (device globals: allocation-free per harness rules)
// ---------------------------------------------------------------------------
__device__ float g_qkv[(size_t)B_ * S_ * F_];          // [B*S, 3072]

__device__ __nv_bfloat16 g_x1[(size_t)B_ * S_ * H_];   // GEMM A hi (hidden, then attn O)
__device__ __nv_bfloat16 g_x2[(size_t)B_ * S_ * H_];   // GEMM A lo
__device__ __nv_bfloat16 g_wa1[(size_t)F_ * H_];       // w_attn^T hi [3072,2048]
__device__ __nv_bfloat16 g_wa2[(size_t)F_ * H_];
__device__ __nv_bfloat16 g_wp1[(size_t)H_ * H_];       // w_proj^T hi [2048,2048]
__device__ __nv_bfloat16 g_wp2[(size_t)H_ * H_];

__device__ __nv_bfloat16 g_qh[(size_t)B_ * NH_ * S_ * HD_];   // Q hi (pre-scaled)
__device__ __nv_bfloat16 g_ql[(size_t)B_ * NH_ * S_ * HD_];
__device__ __nv_bfloat16 g_kh[(size_t)B_ * NKV_ * S_ * HD_];
__device__ __nv_bfloat16 g_kl[(size_t)B_ * NKV_ * S_ * HD_];
__device__ __nv_bfloat16 g_vh[(size_t)B_ * NKV_ * S_ * HD_];
__device__ __nv_bfloat16 g_vl[(size_t)B_ * NKV_ * S_ * HD_];

// ---------------------------------------------------------------------------
// Arch-neutral PTX helpers (tcgen05 unavailable under compute_103 target)
// ---------------------------------------------------------------------------
__device__ __forceinline__ uint32_t smem_u32(const void* p) {
    uint32_t a;
    asm("{ .reg .u64 t; cvta.to.shared.u64 t, %1; cvt.u32.u64 %0, t; }" : "=r"(a) : "l"(p));
    return a;
}
__device__ __forceinline__ void cp16(uint32_t saddr, const void* g) {
    asm volatile("cp.async.cg.shared.global [%0], [%1], 16;" :: "r"(saddr), "l"(g));
}
#define CP_COMMIT() asm volatile("cp.async.commit_group;" ::: "memory")
#define CP_WAIT(n)  asm volatile("cp.async.wait_group %0;" :: "n"(n) : "memory")

__device__ __forceinline__ void ldsm_x4(uint32_t* r, uint32_t addr) {
    asm volatile("ldmatrix.sync.aligned.m8n8.x4.shared.b16 {%0,%1,%2,%3}, [%4];"
                 : "=r"(r[0]), "=r"(r[1]), "=r"(r[2]), "=r"(r[3]) : "r"(addr));
}
__device__ __forceinline__ void ldsm_x4_t(uint32_t* r, uint32_t addr) {
    asm volatile("ldmatrix.sync.aligned.m8n8.x4.trans.shared.b16 {%0,%1,%2,%3}, [%4];"
                 : "=r"(r[0]), "=r"(r[1]), "=r"(r[2]), "=r"(r[3]) : "r"(addr));
}
__device__ __forceinline__ void mma_bf16(float* c, const uint32_t* a, const uint32_t* b) {
    asm volatile(
        "mma.sync.aligned.m16n8k16.row.col.f32.bf16.bf16.f32 "
        "{%0,%1,%2,%3}, {%4,%5,%6,%7}, {%8,%9}, {%0,%1,%2,%3};"
        : "+f"(c[0]), "+f"(c[1]), "+f"(c[2]), "+f"(c[3])
        : "r"(a[0]), "r"(a[1]), "r"(a[2]), "r"(a[3]), "r"(b[0]), "r"(b[1]));
}
__device__ __forceinline__ uint32_t swz(uint32_t off) {  // SW128
    return off ^ ((off >> 3) & 0x70);
}
__device__ __forceinline__ uint32_t pk(__nv_bfloat16 a, __nv_bfloat16 b) {
    uint16_t x = *(uint16_t*)&a, y = *(uint16_t*)&b;
    return ((uint32_t)y << 16) | x;
}
// split (c0,c1) fp32 pair into packed hi/lo bf16x2
__device__ __forceinline__ void split_pk(float c0, float c1, uint32_t& hi, uint32_t& lo) {
    __nv_bfloat16 h0 = __float2bfloat16(c0), h1 = __float2bfloat16(c1);
    hi = pk(h0, h1);
    __nv_bfloat16 l0 = __float2bfloat16(c0 - __bfloat162float(h0));
    __nv_bfloat16 l1 = __float2bfloat16(c1 - __bfloat162float(h1));
    lo = pk(l0, l1);
}

// ---------------------------------------------------------------------------
// bf16 split kernels
// ---------------------------------------------------------------------------
__global__ __launch_bounds__(256) void split2(
    const float* __restrict__ x, __nv_bfloat16* __restrict__ hi,
    __nv_bfloat16* __restrict__ lo, int n4)
{
    int i = blockIdx.x * 256 + threadIdx.x;
    if (i >= n4) return;
    float4 v = *((const float4*)x + i);
    uint32_t h0, l0, h1, l1;
    split_pk(v.x, v.y, h0, l0);
    split_pk(v.z, v.w, h1, l1);
    ((uint32_t*)hi)[i * 2]     = h0;
    ((uint32_t*)hi)[i * 2 + 1] = h1;
    ((uint32_t*)lo)[i * 2]     = l0;
    ((uint32_t*)lo)[i * 2 + 1] = l1;
}

// transpose + split: in [K,N] fp32 row-major -> out [N,K] bf16 (hi, lo)
__global__ __launch_bounds__(256) void tsplit(
    const float* __restrict__ in, __nv_bfloat16* __restrict__ oh,
    __nv_bfloat16* __restrict__ ol, int K, int N)
{
    __shared__ float t[32][33];
    int n0 = blockIdx.x * 32, k0 = blockIdx.y * 32;
    int tx = threadIdx.x & 31, ty = threadIdx.x >> 5;
    #pragma unroll
    for (int r = ty; r < 32; r += 8)
        t[r][tx] = in[(size_t)(k0 + r) * N + n0 + tx];
    __syncthreads();
    #pragma unroll
    for (int r = ty; r < 32; r += 8) {
        float v = t[tx][r];
        __nv_bfloat16 h = __float2bfloat16(v);
        __nv_bfloat16 l = __float2bfloat16(v - __bfloat162float(h));
        size_t off = (size_t)(n0 + r) * K + k0 + tx;
        oh[off] = h;
        ol[off] = l;
    }
}

// ---------------------------------------------------------------------------
// bf16x3 GEMM on mma.sync (unchanged from round 3 — passing, 443 TF/s eff.)
// ---------------------------------------------------------------------------
__global__ __launch_bounds__(256, 1) void gemm_bf16x3(
    const __nv_bfloat16* __restrict__ A1, const __nv_bfloat16* __restrict__ A2,
    const __nv_bfloat16* __restrict__ B1, const __nv_bfloat16* __restrict__ B2,
    float* __restrict__ C, int M, int N, int K)
{
    extern __shared__ __align__(128) char smem[];
    const uint32_t sbase = smem_u32(smem);
    const int tid = threadIdx.x;
    const int wid = tid >> 5, lane = tid & 31;
    const int bm = blockIdx.y * 128, bn = blockIdx.x * 128;

    const __nv_bfloat16* srcs[4] = {
        A1 + (size_t)bm * K, A2 + (size_t)bm * K,
        B1 + (size_t)bn * K, B2 + (size_t)bn * K };

    const int nchunks = K / KC_;

    auto load_stage = [&](int c, int buf) {
        const int k0 = c * KC_;
        #pragma unroll
        for (int t = 0; t < 4; t++) {
            const __nv_bfloat16* g = srcs[t] + k0;
            uint32_t db = sbase + buf * 65536 + t * 16384;
            #pragma unroll
            for (int it = 0; it < 4; it++) {
                int i = tid + it * 256;
                int row = i >> 3, c8 = i & 7;
                cp16(db + swz((uint32_t)(row * 128 + c8 * 16)),
                     g + (size_t)row * K + c8 * 8);
            }
        }
    };

    load_stage(0, 0); CP_COMMIT();
    if (nchunks > 1) load_stage(1, 1);
    CP_COMMIT();

    const int wm = wid >> 2, wn = wid & 3;
    const int m0 = wm * 64, n0 = wn * 32;

    float acc[4][4][4];
    #pragma unroll
    for (int i = 0; i < 4; i++)
        #pragma unroll
        for (int j = 0; j < 4; j++)
            #pragma unroll
            for (int k = 0; k < 4; k++) acc[i][j][k] = 0.f;

    const int aRow = (lane & 15);
    const int aKb  = (lane >> 4) * 16;
    const int bRow = (lane & 7) + ((lane >> 4) & 1) * 8;
    const int bKb  = ((lane >> 3) & 1) * 16;

    for (int c = 0; c < nchunks; c++) {
        CP_WAIT(1);
        __syncthreads();
        const int buf = c & 1;
        const uint32_t sA1 = sbase + buf * 65536;
        const uint32_t sA2 = sA1 + 16384;
        const uint32_t sB1 = sA1 + 32768;
        const uint32_t sB2 = sA1 + 49152;

        #pragma unroll
        for (int ks = 0; ks < 4; ks++) {
            const uint32_t akb = (uint32_t)(ks * 32 + aKb);
            const uint32_t bkb = (uint32_t)(ks * 32 + bKb);
            uint32_t a1f[4][4], a2f[4][4], b1f[2][4], b2f[2][4];
            #pragma unroll
            for (int mt = 0; mt < 4; mt++) {
                uint32_t off = swz((uint32_t)((m0 + mt * 16 + aRow) * 128) + akb);
                ldsm_x4(a1f[mt], sA1 + off);
                ldsm_x4(a2f[mt], sA2 + off);
            }
            #pragma unroll
            for (int p = 0; p < 2; p++) {
                uint32_t off = swz((uint32_t)((n0 + p * 16 + bRow) * 128) + bkb);
                ldsm_x4(b1f[p], sB1 + off);
                ldsm_x4(b2f[p], sB2 + off);
            }
            #pragma unroll
            for (int mt = 0; mt < 4; mt++)
                #pragma unroll
                for (int nt = 0; nt < 4; nt++) {
                    mma_bf16(acc[mt][nt], a1f[mt], &b1f[nt >> 1][(nt & 1) * 2]);
                    mma_bf16(acc[mt][nt], a1f[mt], &b2f[nt >> 1][(nt & 1) * 2]);
                    mma_bf16(acc[mt][nt], a2f[mt], &b1f[nt >> 1][(nt & 1) * 2]);
                }
        }
        __syncthreads();
        if (c + 2 < nchunks) load_stage(c + 2, buf);
        CP_COMMIT();
    }

    const int er = lane >> 2, ec = (lane & 3) * 2;
    #pragma unroll
    for (int mt = 0; mt < 4; mt++)
        #pragma unroll
        for (int nt = 0; nt < 4; nt++) {
            int row = bm + m0 + mt * 16 + er;
            int col = bn + n0 + nt * 8 + ec;
            *(float2*)(C + (size_t)row * N + col) =
                make_float2(acc[mt][nt][0], acc[mt][nt][1]);
            *(float2*)(C + (size_t)(row + 8) * N + col) =
                make_float2(acc[mt][nt][2], acc[mt][nt][3]);
        }
}

// ---------------------------------------------------------------------------
// RoPE + split/scatter -> hi/lo bf16. Q pre-scaled by 1/sqrt(HD).
// ---------------------------------------------------------------------------
__global__ __launch_bounds__(256) void rope_split_bf16(
    const float* __restrict__ qkv, const float* __restrict__ rope_cos,
    const float* __restrict__ rope_sin,
    __nv_bfloat16* __restrict__ qh, __nv_bfloat16* __restrict__ ql,
    __nv_bfloat16* __restrict__ kh, __nv_bfloat16* __restrict__ kl,
    __nv_bfloat16* __restrict__ vh, __nv_bfloat16* __restrict__ vl)
{
    const int tok = blockIdx.x;
    const int b = tok >> 11;
    const int s = tok & 2047;
    const float scale = 0.08838834764831845f;  // 1/sqrt(128)

    __shared__ float shc[HD_], shs[HD_];
    if (threadIdx.x < 128)      shc[threadIdx.x] = rope_cos[(size_t)s * HD_ + threadIdx.x];
    else                        shs[threadIdx.x - 128] = rope_sin[(size_t)s * HD_ + threadIdx.x - 128];
    __syncthreads();

    const float* base = qkv + (size_t)tok * F_;

    for (int idx = threadIdx.x; idx < NH_ * HD_; idx += 256) {
        int hh = idx >> 7, d = idx & 127;
        int j = hh >> 2, i = hh & 3;
        const float* qp = base + j * 768 + i * 128;
        float x = qp[d];
        float other = (d < 64) ? -qp[d + 64] : qp[d - 64];
        float v = (x * shc[d] + other * shs[d]) * scale;
        __nv_bfloat16 h = __float2bfloat16(v);
        size_t off = (((size_t)b * NH_ + hh) * S_ + s) * HD_ + d;
        qh[off] = h;
        ql[off] = __float2bfloat16(v - __bfloat162float(h));
    }
    for (int idx = threadIdx.x; idx < NKV_ * HD_; idx += 256) {
        int j = idx >> 7, d = idx & 127;
        const float* kp = base + j * 768 + 512;
        float x = kp[d];
        float other = (d < 64) ? -kp[d + 64] : kp[d - 64];
        float kv = x * shc[d] + other * shs[d];
        float vv = kp[128 + d];
        size_t off = (((size_t)b * NKV_ + j) * S_ + s) * HD_ + d;
        __nv_bfloat16 hk = __float2bfloat16(kv);
        kh[off] = hk;
        kl[off] = __float2bfloat16(kv - __bfloat162float(hk));
        __nv_bfloat16 hv = __float2bfloat16(vv);
        vh[off] = hv;
        vl[off] = __float2bfloat16(vv - __bfloat162float(hv));
    }
}

// ---------------------------------------------------------------------------
// Tensor-core causal flash attention, bf16x3, GQA.
// CTA: 128 q-rows; 8 warps x 16 rows. Key tiles of 64, double-buffered cp.async.
// Writes O directly as hi/lo bf16 into the proj-GEMM A operands [B,S,NH*HD].
// smem: Qh/Ql 32KB each; per stage Kh/Kl/Vh/Vl 16KB each (2 stages) = 192KB.
// ---------------------------------------------------------------------------
__global__ __launch_bounds__(256, 1) void flash_mma(
    const __nv_bfloat16* __restrict__ Qh, const __nv_bfloat16* __restrict__ Ql,
    const __nv_bfloat16* __restrict__ Kh, const __nv_bfloat16* __restrict__ Kl,
    const __nv_bfloat16* __restrict__ Vh, const __nv_bfloat16* __restrict__ Vl,
    __nv_bfloat16* __restrict__ Oh, __nv_bfloat16* __restrict__ Ol)
{
    extern __shared__ __align__(128) char smem[];
    const uint32_t sb = smem_u32(smem);
    const int tid = threadIdx.x, lane = tid & 31, w = tid >> 5;
    const int qt = (int)(gridDim.x - 1) - (int)blockIdx.x;   // heavy tiles first
    const int h = blockIdx.y, b = blockIdx.z;
    const int kvh = h >> 2;

    const __nv_bfloat16* gQh = Qh + (((size_t)b * NH_ + h) * S_ + (size_t)qt * 128) * HD_;
    const __nv_bfloat16* gQl = Ql + (((size_t)b * NH_ + h) * S_ + (size_t)qt * 128) * HD_;
    const size_t kvbase = ((size_t)b * NKV_ + kvh) * S_ * HD_;
    const __nv_bfloat16* gKh = Kh + kvbase;
    const __nv_bfloat16* gKl = Kl + kvbase;
    const __nv_bfloat16* gVh = Vh + kvbase;
    const __nv_bfloat16* gVl = Vl + kvbase;

    // loaders into chunked SW128 layout ([hd_chunk][row][64 bf16], 128B rows)
    auto loadQ = [&](uint32_t off, const __nv_bfloat16* g) {
        #pragma unroll
        for (int it = 0; it < 8; it++) {
            int i = tid + it * 256;                // 2048 16B chunks
            int row = i >> 4, c8 = i & 15;
            cp16(sb + off + (uint32_t)(c8 >> 3) * 16384 +
                     swz((uint32_t)(row * 128 + (c8 & 7) * 16)),
                 g + (size_t)row * HD_ + c8 * 8);
        }
    };
    auto loadKV = [&](uint32_t off, const __nv_bfloat16* g) {
        #pragma unroll
        for (int it = 0; it < 4; it++) {
            int i = tid + it * 256;                // 1024 16B chunks
            int row = i >> 4, c8 = i & 15;
            cp16(sb + off + (uint32_t)(c8 >> 3) * 8192 +
                     swz((uint32_t)(row * 128 + (c8 & 7) * 16)),
                 g + (size_t)row * HD_ + c8 * 8);
        }
    };
    auto load_stage = [&](int kt, int buf) {
        uint32_t o = 65536 + (uint32_t)buf * 65536;
        const size_t go = (size_t)kt * 64 * HD_;
        loadKV(o,         gKh + go);
        loadKV(o + 16384, gKl + go);
        loadKV(o + 32768, gVh + go);
        loadKV(o + 49152, gVl + go);
    };

    loadQ(0, gQh);
    loadQ(32768, gQl);
    load_stage(0, 0);
    CP_COMMIT();

    const int nkt = 2 * qt + 2;

    float O[16][4];
    #pragma unroll
    for (int i = 0; i < 16; i++)
        #pragma unroll
        for (int j = 0; j < 4; j++) O[i][j] = 0.f;
    float mA = -1e30f, mB = -1e30f, lA = 0.f, lB = 0.f;

    const int aRow = lane & 15;
    const int aK16 = (lane >> 4) * 16;                    // bytes
    const int bRow = (lane & 7) + ((lane >> 4) & 1) * 8;
    const int bK16 = ((lane >> 3) & 1) * 16;              // bytes

    for (int kt = 0; kt < nkt; kt++) {
        const int buf = kt & 1;
        if (kt + 1 < nkt) { load_stage(kt + 1, buf ^ 1); CP_COMMIT(); CP_WAIT(1); }
        else              { CP_WAIT(0); }
        __syncthreads();

        const uint32_t sKh = sb + 65536 + (uint32_t)buf * 65536;
        const uint32_t sKl = sKh + 16384;
        const uint32_t sVh = sKh + 32768;
        const uint32_t sVl = sKh + 49152;

        // ---- S = Q K^T (bf16x3) ----
        float S[8][4];
        #pragma unroll
        for (int i = 0; i < 8; i++)
            #pragma unroll
            for (int j = 0; j < 4; j++) S[i][j] = 0.f;

        #pragma unroll
        for (int ks = 0; ks < 8; ks++) {
            uint32_t qo = (uint32_t)(ks >> 2) * 16384 +
                          swz((uint32_t)((w * 16 + aRow) * 128 + (ks & 3) * 32 + aK16));
            uint32_t qhf[4], qlf[4];
            ldsm_x4(qhf, sb + qo);
            ldsm_x4(qlf, sb + 32768 + qo);
            #pragma unroll
            for (int g = 0; g < 4; g++) {
                uint32_t ko = (uint32_t)(ks >> 2) * 8192 +
                              swz((uint32_t)((g * 16 + bRow) * 128 + (ks & 3) * 32 + bK16));
                uint32_t khf[4], klf[4];
                ldsm_x4(khf, sKh + ko);
                ldsm_x4(klf, sKl + ko);
                #pragma unroll
                for (int p = 0; p < 2; p++) {
                    int nt = g * 2 + p;
                    mma_bf16(S[nt], qhf, &khf[p * 2]);
                    mma_bf16(S[nt], qhf, &klf[p * 2]);
                    mma_bf16(S[nt], qlf, &khf[p * 2]);
                }
            }
        }

        // ---- causal mask (only last two key tiles can cross the diagonal) ----
        if (kt >= 2 * qt) {
            const int rA = qt * 128 + w * 16 + (lane >> 2);
            #pragma unroll
            for (int nt = 0; nt < 8; nt++) {
                int key0 = kt * 64 + nt * 8 + (lane & 3) * 2;
                if (key0     > rA)     S[nt][0] = -1e30f;
                if (key0 + 1 > rA)     S[nt][1] = -1e30f;
                if (key0     > rA + 8) S[nt][2] = -1e30f;
                if (key0 + 1 > rA + 8) S[nt][3] = -1e30f;
            }
        }

        // ---- online softmax ----
        float mxA = -1e30f, mxB = -1e30f;
        #pragma unroll
        for (int nt = 0; nt < 8; nt++) {
            mxA = fmaxf(mxA, fmaxf(S[nt][0], S[nt][1]));
            mxB = fmaxf(mxB, fmaxf(S[nt][2], S[nt][3]));
        }
        #pragma unroll
        for (int off = 1; off < 4; off <<= 1) {
            mxA = fmaxf(mxA, __shfl_xor_sync(0xffffffffu, mxA, off));
            mxB = fmaxf(mxB, __shfl_xor_sync(0xffffffffu, mxB, off));
        }
        float mAn = fmaxf(mA, mxA), mBn = fmaxf(mB, mxB);
        float aAl = __expf(mA - mAn), aBl = __expf(mB - mBn);
        mA = mAn; mB = mBn;

        float sumA = 0.f, sumB = 0.f;
        #pragma unroll
        for (int nt = 0; nt < 8; nt++) {
            S[nt][0] = __expf(S[nt][0] - mA);
            S[nt][1] = __expf(S[nt][1] - mA);
            S[nt][2] = __expf(S[nt][2] - mB);
            S[nt][3] = __expf(S[nt][3] - mB);
            sumA += S[nt][0] + S[nt][1];
            sumB += S[nt][2] + S[nt][3];
        }
        #pragma unroll
        for (int off = 1; off < 4; off <<= 1) {
            sumA += __shfl_xor_sync(0xffffffffu, sumA, off);
            sumB += __shfl_xor_sync(0xffffffffu, sumB, off);
        }
        lA = lA * aAl + sumA;
        lB = lB * aBl + sumB;
        #pragma unroll
        for (int nt = 0; nt < 16; nt++) {
            O[nt][0] *= aAl; O[nt][1] *= aAl;
            O[nt][2] *= aBl; O[nt][3] *= aBl;
        }

        // ---- O += P V (bf16x3; P from S regs, V via ldmatrix.trans) ----
        #pragma unroll
        for (int kk = 0; kk < 4; kk++) {
            uint32_t ah[4], al[4];
            split_pk(S[2 * kk][0],     S[2 * kk][1],     ah[0], al[0]);
            split_pk(S[2 * kk][2],     S[2 * kk][3],     ah[1], al[1]);
            split_pk(S[2 * kk + 1][0], S[2 * kk + 1][1], ah[2], al[2]);
            split_pk(S[2 * kk + 1][2], S[2 * kk + 1][3], ah[3], al[3]);
            #pragma unroll
            for (int g = 0; g < 8; g++) {          // hd cols g*16..+16
                uint32_t vo = (uint32_t)(g >> 2) * 8192 +
                              swz((uint32_t)((kk * 16 + (lane & 15)) * 128 +
                                             (g & 3) * 32 + (lane >> 4) * 16));
                uint32_t vhf[4], vlf[4];
                ldsm_x4_t(vhf, sVh + vo);
                ldsm_x4_t(vlf, sVl + vo);
                #pragma unroll
                for (int p = 0; p < 2; p++) {
                    int nt = g * 2 + p;
                    mma_bf16(O[nt], ah, &vhf[p * 2]);
                    mma_bf16(O[nt], ah, &vlf[p * 2]);
                    mma_bf16(O[nt], al, &vhf[p * 2]);
                }
            }
        }
        __syncthreads();
    }

    // ---- epilogue: O/l -> hi/lo bf16 at [B, S, NH*HD] ----
    const float iA = 1.f / lA, iB = 1.f / lB;
    const int sA = qt * 128 + w * 16 + (lane >> 2);
    const size_t baseA = ((size_t)b * S_ + sA) * H_ + (size_t)h * HD_;
    const size_t baseB = baseA + (size_t)8 * H_;
    #pragma unroll
    for (int nt = 0; nt < 16; nt++) {
        int col = nt * 8 + (lane & 3) * 2;
        uint32_t hi, lo;
        split_pk(O[nt][0] * iA, O[nt][1] * iA, hi, lo);
        *(uint32_t*)(Oh + baseA + col) = hi;
        *(uint32_t*)(Ol + baseA + col) = lo;
        split_pk(O[nt][2] * iB, O[nt][3] * iB, hi, lo);
        *(uint32_t*)(Oh + baseB + col) = hi;
        *(uint32_t*)(Ol + baseB + col) = lo;
    }
}

// ---------------------------------------------------------------------------
// Launch
// ---------------------------------------------------------------------------
extern "C" void kernel_launch(void* const* d_in, const int* in_sizes, int n_in,
                              void* d_out, int out_size)
{
    (void)in_sizes; (void)n_in; (void)out_size;
    const float* hidden   = (const float*)d_in[0];
    // d_in[1] = attention_mask: structurally causal, unused (exp(-1e9) == 0 in fp32)
    const float* rope_cos = (const float*)d_in[2];
    const float* rope_sin = (const float*)d_in[3];
    const float* w_attn   = (const float*)d_in[4];
    const float* w_proj   = (const float*)d_in[5];
    float* out = (float*)d_out;

    float* p_qkv;
    __nv_bfloat16 *p_x1, *p_x2, *p_wa1, *p_wa2, *p_wp1, *p_wp2;
    __nv_bfloat16 *p_qh, *p_ql, *p_kh, *p_kl, *p_vh, *p_vl;
    cudaGetSymbolAddress((void**)&p_qkv, g_qkv);
    cudaGetSymbolAddress((void**)&p_x1, g_x1);
    cudaGetSymbolAddress((void**)&p_x2, g_x2);
    cudaGetSymbolAddress((void**)&p_wa1, g_wa1);
    cudaGetSymbolAddress((void**)&p_wa2, g_wa2);
    cudaGetSymbolAddress((void**)&p_wp1, g_wp1);
    cudaGetSymbolAddress((void**)&p_wp2, g_wp2);
    cudaGetSymbolAddress((void**)&p_qh, g_qh);
    cudaGetSymbolAddress((void**)&p_ql, g_ql);
    cudaGetSymbolAddress((void**)&p_kh, g_kh);
    cudaGetSymbolAddress((void**)&p_kl, g_kl);
    cudaGetSymbolAddress((void**)&p_vh, g_vh);
    cudaGetSymbolAddress((void**)&p_vl, g_vl);

    const int gemm_smem = 2 * 65536;
    cudaFuncSetAttribute(gemm_bf16x3, cudaFuncAttributeMaxDynamicSharedMemorySize, gemm_smem);
    const int flash_smem = 65536 + 2 * 65536;   // 192 KB
    cudaFuncSetAttribute(flash_mma, cudaFuncAttributeMaxDynamicSharedMemorySize, flash_smem);

    const int MTOK = B_ * S_;

    // 0) prep: transpose+split weights, split hidden
    tsplit<<<dim3(F_ / 32, H_ / 32), 256>>>(w_attn, p_wa1, p_wa2, H_, F_);
    tsplit<<<dim3(H_ / 32, H_ / 32), 256>>>(w_proj, p_wp1, p_wp2, H_, H_);
    split2<<<(MTOK * H_ / 4 + 255) / 256, 256>>>(hidden, p_x1, p_x2, MTOK * H_ / 4);

    // 1) QKV projection (tensor cores): [8192,2048] @ [2048,3072]
    gemm_bf16x3<<<dim3(F_ / 128, MTOK / 128), 256, gemm_smem>>>(
        p_x1, p_x2, p_wa1, p_wa2, p_qkv, MTOK, F_, H_);

    // 2) RoPE + split to hi/lo bf16 heads
    rope_split_bf16<<<B_ * S_, 256>>>(p_qkv, rope_cos, rope_sin,
                                      p_qh, p_ql, p_kh, p_kl, p_vh, p_vl);

    // 3) Tensor-core causal flash attention -> x1/x2 (hi/lo) directly
    flash_mma<<<dim3(S_ / 128, NH_, B_), 256, flash_smem>>>(
        p_qh, p_ql, p_kh, p_kl, p_vh, p_vl, p_x1, p_x2);

    // 4) output projection: [8192,2048] @ [2048,2048]
    gemm_bf16x3<<<dim3(H_ / 128, MTOK / 128), 256, gemm_smem>>>(
        p_x1, p_x2, p_wp1, p_wp2, out, MTOK, H_, H_);
}